// round 5
// baseline (speedup 1.0000x reference)
#include <cuda_runtime.h>
#include <cuda_bf16.h>

#define KCODES   512
#define DDIM     64
#define KTILE    128          // codes per smem tile (4 tiles total)
#define NTHREADS 256

// Replicates the reference fp32 arithmetic:
//   dists = fl( fl( ||z||^2 - fl(2 * dot) ) + ||e||^2 ),  dot = sequential FMA over d
// so that quantization ties resolve identically to jax/XLA-CPU.
extern "C" __global__ void __launch_bounds__(NTHREADS)
vq_argmin_kernel(const float* __restrict__ z,
                 const float* __restrict__ cb,
                 float* __restrict__ out,   // __output__ dtype: float32
                 int nrows) {
    __shared__ float sC[KTILE * DDIM];
    __shared__ float sN[KTILE];

    const int r = blockIdx.x * NTHREADS + threadIdx.x;
    const bool active = (r < nrows);

    // z row in registers + ||z||^2 (order-insensitive: uniform shift across row)
    float zr[DDIM];
    float a = 0.f;
    if (active) {
        const float4* gz = reinterpret_cast<const float4*>(z + (size_t)r * DDIM);
        #pragma unroll
        for (int j = 0; j < DDIM / 4; j++) {
            float4 v = gz[j];
            zr[4 * j + 0] = v.x;
            zr[4 * j + 1] = v.y;
            zr[4 * j + 2] = v.z;
            zr[4 * j + 3] = v.w;
        }
        #pragma unroll
        for (int d = 0; d < DDIM; d++) a = fmaf(zr[d], zr[d], a);
    }

    float best = 3.4e38f;
    int bidx = 0;

    for (int tile = 0; tile < KCODES / KTILE; tile++) {
        __syncthreads();
        {   // stage tile of codebook (coalesced float4)
            const float4* gc =
                reinterpret_cast<const float4*>(cb + (size_t)tile * KTILE * DDIM);
            float4* sc4 = reinterpret_cast<float4*>(sC);
            #pragma unroll
            for (int i = threadIdx.x; i < KTILE * DDIM / 4; i += NTHREADS)
                sc4[i] = gc[i];
        }
        __syncthreads();
        // per-code ||e||^2 (error ~1e-11 << rounding grid: order irrelevant)
        for (int k = threadIdx.x; k < KTILE; k += NTHREADS) {
            const float* row = sC + k * DDIM;
            float s = 0.f;
            #pragma unroll
            for (int d = 0; d < DDIM; d++) s = fmaf(row[d], row[d], s);
            sN[k] = s;
        }
        __syncthreads();

        if (active) {
            #pragma unroll 2
            for (int k = 0; k < KTILE; k++) {
                const float4* crow = reinterpret_cast<const float4*>(sC + k * DDIM);
                // dot as a strict SEQUENTIAL fma chain over d (match XLA-CPU k-order)
                float m = 0.f;
                #pragma unroll
                for (int j = 0; j < DDIM / 4; j++) {
                    float4 c = crow[j];   // broadcast LDS.128
                    m = fmaf(zr[4 * j + 0], c.x, m);
                    m = fmaf(zr[4 * j + 1], c.y, m);
                    m = fmaf(zr[4 * j + 2], c.z, m);
                    m = fmaf(zr[4 * j + 3], c.w, m);
                }
                // fl(fl(a - fl(2m)) + n) with NO fma contraction
                float b2 = __fmul_rn(2.0f, m);          // exact
                float s1 = __fsub_rn(a, b2);            // rounds at ulp(~64)
                float sc = __fadd_rn(s1, sN[k]);        // rounds at ulp(~64)
                int kk = tile * KTILE + k;
                if (sc < best) { best = sc; bidx = kk; }  // strict < => first-min
            }
        }
    }

    if (active) out[r] = (float)bidx;   // indices 0..511 exact in fp32
}

extern "C" void kernel_launch(void* const* d_in, const int* in_sizes, int n_in,
                              void* d_out, int out_size) {
    // Disambiguate inputs by size: z_e_x has 8.4M elements, codebook 32768.
    const float* a = (const float*)d_in[0];
    const float* b = (const float*)d_in[1];
    const float* z;
    const float* cb;
    int nrows;
    if (in_sizes[0] >= in_sizes[1]) { z = a; cb = b; nrows = in_sizes[0] / DDIM; }
    else                            { z = b; cb = a; nrows = in_sizes[1] / DDIM; }

    int blocks = (nrows + NTHREADS - 1) / NTHREADS;
    vq_argmin_kernel<<<blocks, NTHREADS>>>(z, cb, (float*)d_out, nrows);
}

// round 6
// speedup vs baseline: 1.2389x; 1.2389x over previous
#include <cuda_runtime.h>
#include <cuda_bf16.h>

#define KCODES   512
#define DDIM     64
#define KTILE    128          // codes per smem tile (4 tiles total)
#define NTHREADS 128
#define ROWSPT   2            // rows per thread (register blocking)

// Bit-exact contract (validated R5, rel_err==0):
//   dot m  = strict sequential fmaf chain over d = 0..63
//   score  = fl( fl( ||z||^2 - fl(2*m) ) + ||e||^2 )  with NO fma contraction
//   argmin = first index attaining the min (strict '<')
extern "C" __global__ void __launch_bounds__(NTHREADS, 3)
vq_argmin_kernel(const float* __restrict__ z,
                 const float* __restrict__ cb,
                 float* __restrict__ out,   // __output__ dtype: float32
                 int nrows) {
    __shared__ float sC[KTILE * DDIM];
    __shared__ float sN[KTILE];

    const int r0 = blockIdx.x * (NTHREADS * ROWSPT) + threadIdx.x;
    const int r1 = r0 + NTHREADS;
    const bool act0 = (r0 < nrows);
    const bool act1 = (r1 < nrows);

    // two z rows in registers + their ||z||^2 (order-insensitive term)
    float zr0[DDIM], zr1[DDIM];
    float a0s = 0.f, a1s = 0.f;
    if (act0) {
        const float4* gz = reinterpret_cast<const float4*>(z + (size_t)r0 * DDIM);
        #pragma unroll
        for (int j = 0; j < DDIM / 4; j++) {
            float4 v = gz[j];
            zr0[4*j+0]=v.x; zr0[4*j+1]=v.y; zr0[4*j+2]=v.z; zr0[4*j+3]=v.w;
        }
        #pragma unroll
        for (int d = 0; d < DDIM; d++) a0s = fmaf(zr0[d], zr0[d], a0s);
    }
    if (act1) {
        const float4* gz = reinterpret_cast<const float4*>(z + (size_t)r1 * DDIM);
        #pragma unroll
        for (int j = 0; j < DDIM / 4; j++) {
            float4 v = gz[j];
            zr1[4*j+0]=v.x; zr1[4*j+1]=v.y; zr1[4*j+2]=v.z; zr1[4*j+3]=v.w;
        }
        #pragma unroll
        for (int d = 0; d < DDIM; d++) a1s = fmaf(zr1[d], zr1[d], a1s);
    }

    float best0 = 3.4e38f, best1 = 3.4e38f;
    int bidx0 = 0, bidx1 = 0;

    for (int tile = 0; tile < KCODES / KTILE; tile++) {
        __syncthreads();
        {   // stage tile of codebook (coalesced float4)
            const float4* gc =
                reinterpret_cast<const float4*>(cb + (size_t)tile * KTILE * DDIM);
            float4* sc4 = reinterpret_cast<float4*>(sC);
            #pragma unroll
            for (int i = threadIdx.x; i < KTILE * DDIM / 4; i += NTHREADS)
                sc4[i] = gc[i];
        }
        __syncthreads();
        // per-code ||e||^2 (error ~1e-11 << comparison rounding grid)
        for (int k = threadIdx.x; k < KTILE; k += NTHREADS) {
            const float* row = sC + k * DDIM;
            float s = 0.f;
            #pragma unroll
            for (int d = 0; d < DDIM; d++) s = fmaf(row[d], row[d], s);
            sN[k] = s;
        }
        __syncthreads();

        #pragma unroll 2
        for (int k = 0; k < KTILE; k++) {
            const float4* crow = reinterpret_cast<const float4*>(sC + k * DDIM);
            // each row: strict SEQUENTIAL fma chain over d (bit-exact contract)
            float m0 = 0.f, m1 = 0.f;
            #pragma unroll
            for (int j = 0; j < DDIM / 4; j++) {
                float4 c = crow[j];   // one broadcast LDS.128 feeds 8 FFMAs
                m0 = fmaf(zr0[4*j+0], c.x, m0);
                m1 = fmaf(zr1[4*j+0], c.x, m1);
                m0 = fmaf(zr0[4*j+1], c.y, m0);
                m1 = fmaf(zr1[4*j+1], c.y, m1);
                m0 = fmaf(zr0[4*j+2], c.z, m0);
                m1 = fmaf(zr1[4*j+2], c.z, m1);
                m0 = fmaf(zr0[4*j+3], c.w, m0);
                m1 = fmaf(zr1[4*j+3], c.w, m1);
            }
            const float nk = sN[k];
            const int kk = tile * KTILE + k;
            // fl(fl(a - fl(2m)) + n), unfused
            float s0 = __fadd_rn(__fsub_rn(a0s, __fmul_rn(2.0f, m0)), nk);
            float s1 = __fadd_rn(__fsub_rn(a1s, __fmul_rn(2.0f, m1)), nk);
            if (s0 < best0) { best0 = s0; bidx0 = kk; }
            if (s1 < best1) { best1 = s1; bidx1 = kk; }
        }
    }

    if (act0) out[r0] = (float)bidx0;   // indices 0..511 exact in fp32
    if (act1) out[r1] = (float)bidx1;
}

extern "C" void kernel_launch(void* const* d_in, const int* in_sizes, int n_in,
                              void* d_out, int out_size) {
    // Disambiguate inputs by size: z_e_x has 8.4M elements, codebook 32768.
    const float* a = (const float*)d_in[0];
    const float* b = (const float*)d_in[1];
    const float* z;
    const float* cb;
    int nrows;
    if (in_sizes[0] >= in_sizes[1]) { z = a; cb = b; nrows = in_sizes[0] / DDIM; }
    else                            { z = b; cb = a; nrows = in_sizes[1] / DDIM; }

    int rows_per_block = NTHREADS * ROWSPT;
    int blocks = (nrows + rows_per_block - 1) / rows_per_block;
    vq_argmin_kernel<<<blocks, NTHREADS>>>(z, cb, (float*)d_out, nrows);
}

// round 7
// speedup vs baseline: 1.3416x; 1.0829x over previous
#include <cuda_runtime.h>
#include <cuda_bf16.h>

#define KCODES   512
#define DDIM     64
#define KTILE    128          // codes per smem tile (4 tiles)
#define NPAIRS   (KTILE / 2)  // 64 code-pairs per tile
#define NTHREADS 128
#define GPAIRS   8            // code-pairs processed concurrently

typedef unsigned long long u64;

// packed fp32x2 FMA: a.lane_i = x.lane_i * y.lane_i + a.lane_i  (IEEE rn per lane)
__device__ __forceinline__ void ffma2(u64 &a, u64 x, u64 y) {
    asm("fma.rn.f32x2 %0, %1, %2, %0;" : "+l"(a) : "l"(x), "l"(y));
}
__device__ __forceinline__ u64 dup2(float x) {   // (x, x)
    u64 r; asm("mov.b64 %0, {%1, %1};" : "=l"(r) : "f"(x)); return r;
}
__device__ __forceinline__ void unpack2(u64 v, float &lo, float &hi) {
    asm("mov.b64 {%0, %1}, %2;" : "=f"(lo), "=f"(hi) : "l"(v));
}

// Bit-exact contract (validated R5/R6, rel_err==0):
//   dot m = strict sequential fmaf chain over d=0..63 (per code, per row)
//   score = fl( fl( ||z||^2 - fl(2*m) ) + ||e||^2 ), unfused
//   argmin = first index attaining min (strict '<', ascending code order)
extern "C" __global__ void __launch_bounds__(NTHREADS, 2)
vq_argmin_kernel(const float* __restrict__ z,
                 const float* __restrict__ cb,
                 float* __restrict__ out,
                 int nrows) {
    // pair-interleaved codebook tile: sP[p][d] = (cb[2p][d], cb[2p+1][d])
    __shared__ float sP[NPAIRS * DDIM * 2];   // 32 KB
    __shared__ float sN[KTILE];               // per-code ||e||^2

    const int r0 = blockIdx.x * (NTHREADS * 2) + threadIdx.x;
    const int r1 = r0 + NTHREADS;
    const bool act0 = (r0 < nrows);
    const bool act1 = (r1 < nrows);

    float zr0[DDIM], zr1[DDIM];
    float a0s = 0.f, a1s = 0.f;
    if (act0) {
        const float4* gz = reinterpret_cast<const float4*>(z + (size_t)r0 * DDIM);
        #pragma unroll
        for (int j = 0; j < DDIM / 4; j++) {
            float4 v = gz[j];
            zr0[4*j+0]=v.x; zr0[4*j+1]=v.y; zr0[4*j+2]=v.z; zr0[4*j+3]=v.w;
        }
        #pragma unroll
        for (int d = 0; d < DDIM; d++) a0s = fmaf(zr0[d], zr0[d], a0s);
    }
    if (act1) {
        const float4* gz = reinterpret_cast<const float4*>(z + (size_t)r1 * DDIM);
        #pragma unroll
        for (int j = 0; j < DDIM / 4; j++) {
            float4 v = gz[j];
            zr1[4*j+0]=v.x; zr1[4*j+1]=v.y; zr1[4*j+2]=v.z; zr1[4*j+3]=v.w;
        }
        #pragma unroll
        for (int d = 0; d < DDIM; d++) a1s = fmaf(zr1[d], zr1[d], a1s);
    }

    float best0 = 3.4e38f, best1 = 3.4e38f;
    int bidx0 = 0, bidx1 = 0;

    for (int tile = 0; tile < KCODES / KTILE; tile++) {
        __syncthreads();
        // ---- stage tile, interleaving code pairs: (A.x,B.x,A.y,B.y)... ----
        {
            const float* gt = cb + (size_t)tile * KTILE * DDIM;
            // work item = (pair p, 4-dim chunk c): 64*16 = 1024 items
            for (int it = threadIdx.x; it < NPAIRS * (DDIM / 4); it += NTHREADS) {
                int p = it >> 4;
                int c = it & 15;
                float4 A = reinterpret_cast<const float4*>(gt + (2*p)   * DDIM)[c];
                float4 B = reinterpret_cast<const float4*>(gt + (2*p+1) * DDIM)[c];
                float4* dst = reinterpret_cast<float4*>(sP + (p * DDIM + 4*c) * 2);
                dst[0] = make_float4(A.x, B.x, A.y, B.y);
                dst[1] = make_float4(A.z, B.z, A.w, B.w);
            }
        }
        __syncthreads();
        // ---- per-code norms from the pair layout ----
        for (int k = threadIdx.x; k < KTILE; k += NTHREADS) {
            const float* col = sP + ((k >> 1) * DDIM) * 2 + (k & 1);
            float s = 0.f;
            #pragma unroll
            for (int d = 0; d < DDIM; d++) s = fmaf(col[2*d], col[2*d], s);
            sN[k] = s;
        }
        __syncthreads();

        // ---- main loop: GPAIRS code-pairs at a time, 2 rows, lanes = codes ----
        for (int pg = 0; pg < NPAIRS; pg += GPAIRS) {
            u64 acc0[GPAIRS], acc1[GPAIRS];
            #pragma unroll
            for (int g = 0; g < GPAIRS; g++) { acc0[g] = 0ull; acc1[g] = 0ull; }

            #pragma unroll
            for (int j = 0; j < DDIM / 2; j++) {
                const int d = 2 * j;
                u64 z0a = dup2(zr0[d]);
                u64 z0b = dup2(zr0[d + 1]);
                u64 z1a = dup2(zr1[d]);
                u64 z1b = dup2(zr1[d + 1]);
                #pragma unroll
                for (int g = 0; g < GPAIRS; g++) {
                    // LDS.128: dims d,d+1 for code-pair pg+g (broadcast)
                    const ulonglong2 q = *reinterpret_cast<const ulonglong2*>(
                        sP + ((pg + g) * DDIM + d) * 2);
                    ffma2(acc0[g], z0a, q.x);
                    ffma2(acc0[g], z0b, q.y);
                    ffma2(acc1[g], z1a, q.x);
                    ffma2(acc1[g], z1b, q.y);
                }
            }

            // ---- epilogue: ascending code order preserves first-min ----
            #pragma unroll
            for (int g = 0; g < GPAIRS; g++) {
                const int klo = (pg + g) * 2;        // within tile
                const int kkA = tile * KTILE + klo;
                float mA0, mA1, mB0, mB1;
                unpack2(acc0[g], mA0, mA1);          // row0: codes klo, klo+1
                unpack2(acc1[g], mB0, mB1);          // row1
                const float nA = sN[klo], nB = sN[klo + 1];

                float sA0 = __fadd_rn(__fsub_rn(a0s, __fmul_rn(2.0f, mA0)), nA);
                float sA1 = __fadd_rn(__fsub_rn(a0s, __fmul_rn(2.0f, mA1)), nB);
                float sB0 = __fadd_rn(__fsub_rn(a1s, __fmul_rn(2.0f, mB0)), nA);
                float sB1 = __fadd_rn(__fsub_rn(a1s, __fmul_rn(2.0f, mB1)), nB);

                if (sA0 < best0) { best0 = sA0; bidx0 = kkA; }
                if (sA1 < best0) { best0 = sA1; bidx0 = kkA + 1; }
                if (sB0 < best1) { best1 = sB0; bidx1 = kkA; }
                if (sB1 < best1) { best1 = sB1; bidx1 = kkA + 1; }
            }
        }
    }

    if (act0) out[r0] = (float)bidx0;
    if (act1) out[r1] = (float)bidx1;
}

extern "C" void kernel_launch(void* const* d_in, const int* in_sizes, int n_in,
                              void* d_out, int out_size) {
    // Disambiguate inputs by size: z_e_x 8.4M elements, codebook 32768.
    const float* a = (const float*)d_in[0];
    const float* b = (const float*)d_in[1];
    const float* z;
    const float* cb;
    int nrows;
    if (in_sizes[0] >= in_sizes[1]) { z = a; cb = b; nrows = in_sizes[0] / DDIM; }
    else                            { z = b; cb = a; nrows = in_sizes[1] / DDIM; }

    int rows_per_block = NTHREADS * 2;
    int blocks = (nrows + rows_per_block - 1) / rows_per_block;
    vq_argmin_kernel<<<blocks, NTHREADS>>>(z, cb, (float*)d_out, nrows);
}